// round 2
// baseline (speedup 1.0000x reference)
#include <cuda_runtime.h>
#include <math.h>

#define B     4
#define T     16
#define HID   64
#define HW    64
#define PLANE 4096   // 64*64

// Inter-layer sequence buffers + cell-state scratch (allocation-free rule:
// __device__ globals). 67 MB + 67 MB + 4 MB.
__device__ float g_buf0[(size_t)B * T * HID * PLANE];
__device__ float g_buf1[(size_t)B * T * HID * PLANE];
__device__ float g_c[(size_t)B * HID * PLANE];

__device__ __forceinline__ float sigm(float v) { return 1.f / (1.f + expf(-v)); }

// One fused step: gates = conv3x3_dil([xt; h_{t-1}]) + b ; LSTM update ; residual.
// h_{t-1} is read from the output sequence at t-1 (carry == stored output).
// Block: 2 hid channels x 256 pixels (4 rows x 64 cols). Thread: 1 hid ch x 4 px.
template <int LAYER, int CIN_X, int DIL>
__global__ void __launch_bounds__(128) lstm_step(
    const float* __restrict__ x_in,   // x_seq (used by layer 0 only)
    const float* __restrict__ gw,     // [4*HID][CIN_X+HID][3][3]
    const float* __restrict__ gb,     // [4*HID]
    const float* __restrict__ rw,     // [HID][CIN_X] (layer 0) or null
    const float* __restrict__ rb,     // [HID] or null
    float* __restrict__ out_final,    // d_out (written by layer 2)
    int t)
{
    constexpr int CC = CIN_X + HID;   // concat channels
    constexpr int W9 = CC * 9;

    __shared__ float ws[2][4][W9];    // [co_local][gate][ci*9+k]
    __shared__ float rws[2][CIN_X];   // layer-0 residual 1x1 weights

    const int tid      = threadIdx.x;         // 0..127
    const int ytile    = blockIdx.x;          // 0..15 (4 rows each)
    const int co_group = blockIdx.y;          // 0..31 (2 hid ch each)
    const int b        = blockIdx.z;          // 0..3
    const int co_local = tid >> 6;            // 0..1
    const int s        = tid & 63;
    const int row      = ytile * 4 + (s >> 4);
    const int x0       = (s & 15) << 2;       // 4 px per thread
    const int co       = co_group * 2 + co_local;

    // Cooperative weight stage (warp-uniform broadcast reads later).
    for (int i = tid; i < 8 * W9; i += 128) {
        int cl = i / (4 * W9);
        int r  = i - cl * 4 * W9;
        int gi = r / W9;
        int k  = r - gi * W9;
        ws[cl][gi][k] = gw[(size_t)(gi * HID + co_group * 2 + cl) * W9 + k];
    }
    if (LAYER == 0 && tid < 2 * CIN_X) {
        rws[tid / CIN_X][tid % CIN_X] =
            rw[(co_group * 2 + tid / CIN_X) * CIN_X + (tid % CIN_X)];
    }
    __syncthreads();

    const float* seq_in  = (LAYER == 0) ? x_in : ((LAYER == 1) ? g_buf0 : g_buf1);
    float*       seq_out = (LAYER == 0) ? g_buf0 : ((LAYER == 1) ? g_buf1 : out_final);

    const float* xt = seq_in + (size_t)(b * T + t) * CIN_X * PLANE;
    const float* hp = seq_out + (size_t)(b * T + (t - 1)) * HID * PLANE; // only valid t>0
    const int ctot  = (t > 0) ? CC : CIN_X;   // h==0 at t=0: skip h channels entirely

    float acc[4][4] = {};                     // [gate][px]

    for (int ci = 0; ci < ctot; ci++) {
        const float* plane = (ci < CIN_X) ? (xt + (size_t)ci * PLANE)
                                          : (hp + (size_t)(ci - CIN_X) * PLANE);
#pragma unroll
        for (int ky = 0; ky < 3; ky++) {
            const int yy = row + (ky - 1) * DIL;
            if (yy < 0 || yy >= HW) continue;  // zero padding
            const float* rp = plane + yy * HW;
            float vals[4 + 2 * DIL];
#pragma unroll
            for (int j = 0; j < 4 + 2 * DIL; j++) {
                int xx = x0 - DIL + j;
                vals[j] = (xx >= 0 && xx < HW) ? __ldg(rp + xx) : 0.f;
            }
#pragma unroll
            for (int kx = 0; kx < 3; kx++) {
#pragma unroll
                for (int g = 0; g < 4; g++) {
                    const float w = ws[co_local][g][ci * 9 + ky * 3 + kx];
#pragma unroll
                    for (int px = 0; px < 4; px++)
                        acc[g][px] = fmaf(w, vals[px + kx * DIL], acc[g][px]);
                }
            }
        }
    }

    // Bias
    float gbv[4];
#pragma unroll
    for (int g = 0; g < 4; g++) gbv[g] = __ldg(gb + g * HID + co);

    // Residual
    float res[4];
    if (LAYER == 0) {
        float rbv = __ldg(rb + co);
#pragma unroll
        for (int px = 0; px < 4; px++) res[px] = rbv;
        for (int ci = 0; ci < CIN_X; ci++) {
            float w        = rws[co_local][ci];
            const float* p = xt + (size_t)ci * PLANE + row * HW + x0;
#pragma unroll
            for (int px = 0; px < 4; px++) res[px] = fmaf(w, __ldg(p + px), res[px]);
        }
    } else {
        const float* p = xt + (size_t)co * PLANE + row * HW + x0;
#pragma unroll
        for (int px = 0; px < 4; px++) res[px] = __ldg(p + px);
    }

    float* cptr = g_c + (size_t)(b * HID + co) * PLANE + row * HW + x0;
    float* optr = seq_out + ((size_t)(b * T + t) * HID + co) * PLANE + row * HW + x0;

#pragma unroll
    for (int px = 0; px < 4; px++) {
        float iv    = sigm(acc[0][px] + gbv[0]);
        float fv    = sigm(acc[1][px] + gbv[1]);
        float gv    = tanhf(acc[2][px] + gbv[2]);
        float ov    = sigm(acc[3][px] + gbv[3]);
        float c_old = (t > 0) ? cptr[px] : 0.f;
        float c_new = fv * c_old + iv * gv;
        float h_new = ov * tanhf(c_new);
        cptr[px] = c_new;
        optr[px] = h_new + res[px];
    }
}

extern "C" void kernel_launch(void* const* d_in, const int* in_sizes, int n_in,
                              void* d_out, int out_size)
{
    (void)in_sizes; (void)n_in; (void)out_size;
    const float* x   = (const float*)d_in[0];
    const float* gw0 = (const float*)d_in[1];
    const float* gb0 = (const float*)d_in[2];
    const float* gw1 = (const float*)d_in[3];
    const float* gb1 = (const float*)d_in[4];
    const float* gw2 = (const float*)d_in[5];
    const float* gb2 = (const float*)d_in[6];
    const float* rw0 = (const float*)d_in[7];
    const float* rb0 = (const float*)d_in[8];
    float* out = (float*)d_out;

    dim3 grid(16, 32, B);   // y-tiles x co-groups x batch
    for (int t = 0; t < T; t++)
        lstm_step<0, 32, 1><<<grid, 128>>>(x, gw0, gb0, rw0, rb0, out, t);
    for (int t = 0; t < T; t++)
        lstm_step<1, 64, 2><<<grid, 128>>>(x, gw1, gb1, nullptr, nullptr, out, t);
    for (int t = 0; t < T; t++)
        lstm_step<2, 64, 4><<<grid, 128>>>(x, gw2, gb2, nullptr, nullptr, out, t);
}